// round 11
// baseline (speedup 1.0000x reference)
#include <cuda_runtime.h>

#define NN   32
#define CIN  32
#define COUT 16
#define DD   16
#define WH   256
#define MM   8192   // CIN*WH
#define EPSF 1e-6f

// Scratch (device globals: allocation-free per harness rules)
__device__ float d_b[(size_t)NN * MM * COUT];      // 16 MB routing logits (L2-resident)
__device__ float d_pmax[NN * COUT * CIN];          // per-(n,o,c) partial max
__device__ float d_psum[NN * COUT * CIN];          // per-(n,o,c) partial sumexp
__device__ float d_sc[(size_t)NN * CIN * 256];     // per-(n,c) contribution to s[o,ik]

typedef unsigned long long ull;

// packed-f32x2 helpers
__device__ __forceinline__ ull pack2(float x) {
    ull p;
    asm("mov.b64 %0, {%1, %1};" : "=l"(p) : "r"(__float_as_uint(x)));
    return p;
}
__device__ __forceinline__ void fma2(ull& acc, ull a, ull b) {
    asm("fma.rn.f32x2 %0, %1, %2, %0;" : "+l"(acc) : "l"(a), "l"(b));
}
__device__ __forceinline__ void unpack2(ull v, float& lo, float& hi) {
    unsigned ulo, uhi;
    asm("mov.b64 {%0, %1}, %2;" : "=r"(ulo), "=r"(uhi) : "l"(v));
    lo = __uint_as_float(ulo); hi = __uint_as_float(uhi);
}

// ---------------------------------------------------------------------------
// b-pass: [update: g = squash(sum_c d_sc)]; H_t = W·g (smem, 1KB);
// b (+)= <L, H_t> (b from/to gmem); fused softmax partial stats.
// grid (CIN, NN), 256 threads.
// ---------------------------------------------------------------------------
__global__ void k_bpass(const float* __restrict__ l,
                        const float* __restrict__ g0,
                        const float* __restrict__ wgt,
                        int is_update)
{
    const int c = blockIdx.x, n = blockIdx.y;
    const int tid = threadIdx.x;

    __shared__ __align__(16) float Hsm[256];   // H_t[(i*4+j)*16 + o]
    __shared__ float gsm[256];                 // g[o*16 + ik]
    __shared__ float red[COUT][8];
    __shared__ float gmaxs[COUT];

    if (is_update) {
        // squash prologue: s[tid] = sum_c d_sc[n][c][tid], then squash per o
        float sv = 0.f;
        const float* sp = d_sc + (size_t)n * CIN * 256 + tid;
        #pragma unroll
        for (int c2 = 0; c2 < CIN; c2++) sv += sp[c2 * 256];
        float sq = sv * sv;
        #pragma unroll
        for (int off = 8; off; off >>= 1)
            sq += __shfl_xor_sync(0xffffffffu, sq, off);   // 16-lane group = one o
        const float coef = sq / (1.f + sq) / (sqrtf(sq) + EPSF);
        gsm[tid] = coef * sv;
        __syncthreads();
    }

    // H_t element: H[(i*4+j)*16+o] = sum_k W[c,o,j,k] * g[o, i*4+k]
    {
        const int o = tid >> 4, i = (tid >> 2) & 3, j = tid & 3;
        const float* wp = wgt + ((size_t)(c * COUT + o) * 4 + j) * 4;
        const float* gp = is_update ? (gsm + o * 16 + i * 4)
                                    : (g0 + (size_t)(n * COUT + o) * DD + i * 4);
        float h = 0.f;
        #pragma unroll
        for (int k = 0; k < 4; k++) h = fmaf(wp[k], gp[k], h);
        Hsm[(i * 4 + j) * 16 + o] = h;
    }
    __syncthreads();

    // Load L[t] = l[n,c,d=t,s=tid]
    float L[16];
    const float* lp = l + ((size_t)(n * CIN + c) * DD) * WH + tid;
    #pragma unroll
    for (int t = 0; t < 16; t++) L[t] = lp[t * WH];

    float* brow = d_b + (size_t)(n * MM + c * WH + tid) * COUT;
    ull acc[8];
    if (is_update) {
        #pragma unroll
        for (int p = 0; p < 8; p++)
            acc[p] = *reinterpret_cast<const ull*>(brow + 2 * p);
    } else {
        #pragma unroll
        for (int p = 0; p < 8; p++) acc[p] = 0ull;
    }

    // b += <L, H_t>: H-pairs read directly as ull (no repacking MOVs)
    #pragma unroll
    for (int t = 0; t < 16; t++) {
        ull Lt = pack2(L[t]);
        #pragma unroll
        for (int p = 0; p < 8; p++) {
            ull h = *reinterpret_cast<const ull*>(&Hsm[t * 16 + 2 * p]);
            fma2(acc[p], Lt, h);
        }
    }

    float b[16];
    #pragma unroll
    for (int p = 0; p < 8; p++) {
        unpack2(acc[p], b[2 * p], b[2 * p + 1]);
        *reinterpret_cast<ull*>(brow + 2 * p) = acc[p];
    }

    // Block-level softmax partials per o: max, then sum exp(b - max)
    const int lane = tid & 31, warp = tid >> 5;
    #pragma unroll
    for (int o = 0; o < 16; o++) {
        float v = b[o];
        #pragma unroll
        for (int off = 16; off; off >>= 1)
            v = fmaxf(v, __shfl_xor_sync(0xffffffffu, v, off));
        if (lane == 0) red[o][warp] = v;
    }
    __syncthreads();
    if (tid < 16) {
        float v = red[tid][0];
        #pragma unroll
        for (int w = 1; w < 8; w++) v = fmaxf(v, red[tid][w]);
        gmaxs[tid] = v;
    }
    __syncthreads();
    #pragma unroll
    for (int o = 0; o < 16; o++) {
        float e = __expf(b[o] - gmaxs[o]);
        #pragma unroll
        for (int off = 16; off; off >>= 1)
            e += __shfl_xor_sync(0xffffffffu, e, off);
        if (lane == 0) red[o][warp] = e;
    }
    __syncthreads();
    if (tid < 16) {
        float e = 0.f;
        #pragma unroll
        for (int w = 0; w < 8; w++) e += red[tid][w];
        d_pmax[(n * COUT + tid) * CIN + c] = gmaxs[tid];
        d_psum[(n * COUT + tid) * CIN + c] = e;
    }
}

// ---------------------------------------------------------------------------
// s-pass: finalize softmax stats; load b; cc = softmax(b);
// T[ij,o] = sum_s cc[s,o]*L[s,ij]; sc[o,ik] = sum_j W[c,o,j,k]*T[i4+j,o].
// Optionally emit a = cc. grid (CIN, NN), 256 threads. smem ~44KB.
// ---------------------------------------------------------------------------
__global__ void k_spass(const float* __restrict__ l,
                        const float* __restrict__ wgt,
                        float* __restrict__ a_out,
                        int write_a)
{
    const int c = blockIdx.x, n = blockIdx.y;
    const int tid = threadIdx.x;

    __shared__ __align__(16) float ccs[256][18];   // cc[s][o], 8B-aligned pairs
    __shared__ __align__(16) float Ls[256][18];    // L[s][ij]
    __shared__ float Tpart[8][256];                // per-warp chunk partials
    __shared__ float smax[16], sinv[16];

    // Fused finalize: combine 32 per-c softmax partials for this n
    {
        const int o = tid >> 4, ch = tid & 15;
        const float* pmp = d_pmax + (size_t)(n * COUT + o) * CIN + ch;
        const float* psp = d_psum + (size_t)(n * COUT + o) * CIN + ch;
        float m0 = pmp[0], m1 = pmp[16];
        float gm = fmaxf(m0, m1);
        #pragma unroll
        for (int off = 8; off; off >>= 1)
            gm = fmaxf(gm, __shfl_xor_sync(0xffffffffu, gm, off));
        float e = psp[0] * __expf(m0 - gm) + psp[16] * __expf(m1 - gm);
        #pragma unroll
        for (int off = 8; off; off >>= 1)
            e += __shfl_xor_sync(0xffffffffu, e, off);
        if (ch == 0) { smax[o] = gm; sinv[o] = 1.0f / e; }
    }

    const float* lp = l + ((size_t)(n * CIN + c) * DD) * WH + tid;
    #pragma unroll
    for (int t = 0; t < 16; t++) Ls[tid][t] = lp[t * WH];

    // Load b (4x LDG.128, L2-resident)
    float b[16];
    const float* brow = d_b + (size_t)(n * MM + c * WH + tid) * COUT;
    #pragma unroll
    for (int o = 0; o < 16; o += 4) {
        float4 bv = *reinterpret_cast<const float4*>(brow + o);
        b[o] = bv.x; b[o+1] = bv.y; b[o+2] = bv.z; b[o+3] = bv.w;
    }
    __syncthreads();   // smax/sinv + Ls visible

    float cc[16];
    #pragma unroll
    for (int o = 0; o < 16; o++) {
        cc[o] = __expf(b[o] - smax[o]) * sinv[o];
        ccs[tid][o] = cc[o];
    }
    if (write_a) {
        float* ap = a_out + (size_t)(n * MM + c * WH + tid) * COUT;
        #pragma unroll
        for (int o = 0; o < 16; o += 4)
            *reinterpret_cast<float4*>(ap + o) =
                make_float4(cc[o], cc[o+1], cc[o+2], cc[o+3]);
    }
    __syncthreads();

    // Phase 2: warp = one 32-s chunk (s uniform across warp -> broadcast LDS).
    // lane: p = lane&7 (o-pair 2p,2p+1), q = lane>>3 (cols 4q..4q+3).
    {
        const int w = tid >> 5, lane = tid & 31;
        const int p = lane & 7, q = lane >> 3;
        ull a2[4];
        #pragma unroll
        for (int e = 0; e < 4; e++) a2[e] = 0ull;
        const int s0 = w * 32;
        #pragma unroll 4
        for (int s = s0; s < s0 + 32; s++) {
            ull ccp = *reinterpret_cast<const ull*>(&ccs[s][2 * p]);
            ull l01 = *reinterpret_cast<const ull*>(&Ls[s][4 * q]);
            ull l23 = *reinterpret_cast<const ull*>(&Ls[s][4 * q + 2]);
            float l0, l1, l2, l3;
            unpack2(l01, l0, l1);
            unpack2(l23, l2, l3);
            fma2(a2[0], pack2(l0), ccp);
            fma2(a2[1], pack2(l1), ccp);
            fma2(a2[2], pack2(l2), ccp);
            fma2(a2[3], pack2(l3), ccp);
        }
        #pragma unroll
        for (int e = 0; e < 4; e++)
            *reinterpret_cast<ull*>(&Tpart[w][(4 * q + e) * 16 + 2 * p]) = a2[e];
    }
    __syncthreads();
    {
        float v = 0.f;
        #pragma unroll
        for (int w = 0; w < 8; w++) v += Tpart[w][tid];
        Tpart[0][tid] = v;   // Tsm[ij*16+o], own slot only
    }
    __syncthreads();
    // Per-c contribution to s: sc[o,ik] = sum_j W[c,o,j,k] * T[i*4+j, o]
    {
        const float* Tsm = &Tpart[0][0];
        const int o = tid >> 4, ik = tid & 15, i = ik >> 2, k = ik & 3;
        const float* wp = wgt + (size_t)((c * COUT + o) * 4) * 4;
        float contrib = 0.f;
        #pragma unroll
        for (int j = 0; j < 4; j++)
            contrib = fmaf(wp[j * 4 + k], Tsm[(i * 4 + j) * 16 + o], contrib);
        d_sc[((size_t)n * CIN + c) * 256 + tid] = contrib;
    }
}

// ---------------------------------------------------------------------------
// Final g output: g = squash(sum_c d_sc). grid NN, 256 threads.
// ---------------------------------------------------------------------------
__global__ void k_gfinal(float* __restrict__ g_out)
{
    const int n = blockIdx.x;
    const int tid = threadIdx.x;
    float sv = 0.f;
    const float* sp = d_sc + (size_t)n * CIN * 256 + tid;
    #pragma unroll
    for (int c = 0; c < CIN; c++) sv += sp[c * 256];
    float sq = sv * sv;
    #pragma unroll
    for (int off = 8; off; off >>= 1)
        sq += __shfl_xor_sync(0xffffffffu, sq, off);
    const float coef = sq / (1.f + sq) / (sqrtf(sq) + EPSF);
    g_out[(size_t)n * 256 + tid] = coef * sv;
}

// ---------------------------------------------------------------------------
extern "C" void kernel_launch(void* const* d_in, const int* in_sizes, int n_in,
                              void* d_out, int out_size)
{
    (void)in_sizes; (void)n_in; (void)out_size;
    const float* l = (const float*)d_in[0];
    const float* g = (const float*)d_in[1];
    const float* w = (const float*)d_in[2];
    float* out   = (float*)d_out;
    float* a_out = out;                              // [N, M, COUT]
    float* g_out = out + (size_t)NN * MM * COUT;     // [N, COUT, DD]

    dim3 grid(CIN, NN);
    k_bpass<<<grid, 256>>>(l, g, w, 0);
    for (int it = 0; it < 3; it++) {
        const int last = (it == 2);
        k_spass<<<grid, 256>>>(l, w, a_out, last);
        if (!last) k_bpass<<<grid, 256>>>(l, g, w, 1);
    }
    k_gfinal<<<NN, 256>>>(g_out);
}

// round 12
// speedup vs baseline: 2.1036x; 2.1036x over previous
#include <cuda_runtime.h>

#define NN   32
#define CIN  32
#define COUT 16
#define WH   256
#define MM   8192   // CIN*WH
#define EPSF 1e-6f

// Scratch (device globals). Double-buffered partials: k_iter reads parity
// (wpar^1), writes parity wpar -> no intra-launch producer/consumer race.
__device__ float d_Hc[NN * CIN * 256];             // cumulative H[n][c][ij*16+o]
__device__ float d_pmax[2][NN * COUT * CIN];       // per-(n,o,c) local max K
__device__ float d_psum[2][NN * COUT * CIN];       // per-(n,o,c) sum exp(b-K)
__device__ float d_sc[2][(size_t)NN * CIN * 256];  // per-(n,c) unnormalized s-contrib

typedef unsigned long long ull;

__device__ __forceinline__ ull pack2(float x) {
    ull p;
    asm("mov.b64 %0, {%1, %1};" : "=l"(p) : "r"(__float_as_uint(x)));
    return p;
}
__device__ __forceinline__ void fma2(ull& acc, ull a, ull b) {
    asm("fma.rn.f32x2 %0, %1, %2, %0;" : "+l"(acc) : "l"(a), "l"(b));
}
__device__ __forceinline__ void unpack2(ull v, float& lo, float& hi) {
    unsigned ulo, uhi;
    asm("mov.b64 {%0, %1}, %2;" : "=r"(ulo), "=r"(uhi) : "l"(v));
    lo = __uint_as_float(ulo); hi = __uint_as_float(uhi);
}

// ---------------------------------------------------------------------------
// One fused routing iteration. grid (CIN, NN), 256 threads.
//  it>0: finalize prev softmax stats; g = squash(rescaled sum of sc partials)
//  H_t = W·g; Hcum += H_t; b = <L, Hcum>  (single beval per iteration)
//  K = block max(b); e = exp(b-K); write K, sum(e) partials
//  T_u = sum_s e*L; sc_u = W-contract(T_u) -> d_sc[wpar]
//  write_a: store unnormalized e to a_out (k_fin rescales)
// ---------------------------------------------------------------------------
__global__ void __launch_bounds__(256, 4)
k_iter(const float* __restrict__ l,
       const float* __restrict__ g0,
       const float* __restrict__ wgt,
       float* __restrict__ a_out,
       int it, int wpar, int write_a)
{
    const int c = blockIdx.x, n = blockIdx.y;
    const int tid = threadIdx.x;
    const int lane = tid & 31, warp = tid >> 5;

    __shared__ __align__(16) float ccs[256][18];   // e[s][o]
    __shared__ __align__(16) float Ls[256][18];    // L[s][ij]
    __shared__ float Tpart[8][256];                // per-warp T partials
    __shared__ float Hsm[256];                     // Hcum[(ij)*16+o]
    __shared__ float gsm[256];                     // g[o*16+ik]
    __shared__ float red[COUT][8];
    __shared__ float kms[COUT];                    // local block max
    __shared__ float kmaxs[COUT], sinvs[COUT];     // prologue global stats

    if (it > 0) {
        const int rpar = wpar ^ 1;
        // Finalize global Kmax / S for this n from 32 per-c partials
        {
            const int o = tid >> 4, ch = tid & 15;
            const float* pmp = d_pmax[rpar] + (n * COUT + o) * CIN + ch;
            const float* psp = d_psum[rpar] + (n * COUT + o) * CIN + ch;
            float m0 = pmp[0], m1 = pmp[16];
            float gm = fmaxf(m0, m1);
            #pragma unroll
            for (int off = 8; off; off >>= 1)
                gm = fmaxf(gm, __shfl_xor_sync(0xffffffffu, gm, off));
            float e = psp[0] * __expf(m0 - gm) + psp[16] * __expf(m1 - gm);
            #pragma unroll
            for (int off = 8; off; off >>= 1)
                e += __shfl_xor_sync(0xffffffffu, e, off);
            if (ch == 0) { kmaxs[o] = gm; sinvs[o] = 1.0f / e; }
        }
        __syncthreads();
        // g = squash( (sum_c sc_u[c]*exp(K_c-Kmax)) / S )
        {
            const int o = tid >> 4;
            const float Km = kmaxs[o], Si = sinvs[o];
            const float* sp = d_sc[rpar] + (size_t)n * CIN * 256;
            const float* pm = d_pmax[rpar] + (n * COUT + o) * CIN;
            float sv = 0.f;
            #pragma unroll
            for (int c2 = 0; c2 < CIN; c2++) {
                float f = __expf(pm[c2] - Km);
                sv = fmaf(sp[c2 * 256 + tid], f, sv);
            }
            sv *= Si;
            float sq = sv * sv;
            #pragma unroll
            for (int off = 8; off; off >>= 1)
                sq += __shfl_xor_sync(0xffffffffu, sq, off);
            const float coef = sq / (1.f + sq) / (sqrtf(sq) + EPSF);
            gsm[tid] = coef * sv;
        }
        __syncthreads();
    }

    // H_t element + Hcum update (own slice only; L1 flushed per launch)
    {
        const int o = tid >> 4, i = (tid >> 2) & 3, j = tid & 3;
        const float* wp = wgt + ((size_t)(c * COUT + o) * 4 + j) * 4;
        const float* gp = (it > 0) ? (gsm + o * 16 + i * 4)
                                   : (g0 + (size_t)(n * COUT + o) * 16 + i * 4);
        float h = 0.f;
        #pragma unroll
        for (int k = 0; k < 4; k++) h = fmaf(wp[k], gp[k], h);
        const int idx = (i * 4 + j) * 16 + o;
        float* hc = d_Hc + (size_t)(n * CIN + c) * 256;
        if (it > 0) h += hc[idx];
        hc[idx] = h;
        Hsm[idx] = h;
    }

    // Load L[t] = l[n,c,t,s=tid]; stash to Ls for phase 2
    float L[16];
    const float* lp = l + ((size_t)(n * CIN + c) * 16) * WH + tid;
    #pragma unroll
    for (int t = 0; t < 16; t++) { L[t] = lp[t * WH]; Ls[tid][t] = L[t]; }
    __syncthreads();   // Hsm (+gsm consumed) ready

    // b = <L, Hcum>: the one beval per iteration
    ull acc[8];
    #pragma unroll
    for (int p = 0; p < 8; p++) acc[p] = 0ull;
    #pragma unroll
    for (int t = 0; t < 16; t++) {
        ull Lt = pack2(L[t]);
        #pragma unroll
        for (int p = 0; p < 8; p++)
            fma2(acc[p], Lt, *reinterpret_cast<const ull*>(&Hsm[t * 16 + 2 * p]));
    }

    // Local (block) max per o
    #pragma unroll
    for (int p = 0; p < 8; p++) {
        float b0, b1;
        unpack2(acc[p], b0, b1);
        #pragma unroll
        for (int off = 16; off; off >>= 1) {
            b0 = fmaxf(b0, __shfl_xor_sync(0xffffffffu, b0, off));
            b1 = fmaxf(b1, __shfl_xor_sync(0xffffffffu, b1, off));
        }
        if (lane == 0) { red[2 * p][warp] = b0; red[2 * p + 1][warp] = b1; }
    }
    __syncthreads();
    if (tid < 16) {
        float v = red[tid][0];
        #pragma unroll
        for (int w = 1; w < 8; w++) v = fmaxf(v, red[tid][w]);
        kms[tid] = v;
    }
    __syncthreads();

    // e = exp(b - K); stash to ccs; block-sum partials
    #pragma unroll
    for (int p = 0; p < 8; p++) {
        float b0, b1;
        unpack2(acc[p], b0, b1);
        float e0 = __expf(b0 - kms[2 * p]);
        float e1 = __expf(b1 - kms[2 * p + 1]);
        ccs[tid][2 * p] = e0;
        ccs[tid][2 * p + 1] = e1;
        #pragma unroll
        for (int off = 16; off; off >>= 1) {
            e0 += __shfl_xor_sync(0xffffffffu, e0, off);
            e1 += __shfl_xor_sync(0xffffffffu, e1, off);
        }
        if (lane == 0) { red[2 * p][warp] = e0; red[2 * p + 1][warp] = e1; }
    }
    __syncthreads();
    if (tid < 16) {
        float e = 0.f;
        #pragma unroll
        for (int w = 0; w < 8; w++) e += red[tid][w];
        d_pmax[wpar][(n * COUT + tid) * CIN + c] = kms[tid];
        d_psum[wpar][(n * COUT + tid) * CIN + c] = e;
    }
    if (write_a) {   // unnormalized e; k_fin rescales
        float* ap = a_out + (size_t)(n * MM + c * WH + tid) * COUT;
        #pragma unroll
        for (int p = 0; p < 8; p++)
            *reinterpret_cast<ull*>(ap + 2 * p) =
                *reinterpret_cast<const ull*>(&ccs[tid][2 * p]);
    }

    // Phase 2: T_u[ij,o] = sum_s e[s,o]*L[s,ij]. warp = own 32-s chunk.
    {
        const int p = lane & 7, q = lane >> 3;
        ull a2[4];
        #pragma unroll
        for (int e = 0; e < 4; e++) a2[e] = 0ull;
        const int s0 = warp * 32;
        #pragma unroll 4
        for (int s = s0; s < s0 + 32; s++) {
            ull ccp = *reinterpret_cast<const ull*>(&ccs[s][2 * p]);
            ull l01 = *reinterpret_cast<const ull*>(&Ls[s][4 * q]);
            ull l23 = *reinterpret_cast<const ull*>(&Ls[s][4 * q + 2]);
            float l0, l1, l2, l3;
            unpack2(l01, l0, l1);
            unpack2(l23, l2, l3);
            fma2(a2[0], pack2(l0), ccp);
            fma2(a2[1], pack2(l1), ccp);
            fma2(a2[2], pack2(l2), ccp);
            fma2(a2[3], pack2(l3), ccp);
        }
        #pragma unroll
        for (int e = 0; e < 4; e++)
            *reinterpret_cast<ull*>(&Tpart[warp][(4 * q + e) * 16 + 2 * p]) = a2[e];
    }
    __syncthreads();
    {
        float v = 0.f;
        #pragma unroll
        for (int w = 0; w < 8; w++) v += Tpart[w][tid];
        Tpart[0][tid] = v;   // T_u[ij*16+o]
    }
    __syncthreads();
    // sc_u[o,ik] = sum_j W[c,o,j,k] * T_u[i*4+j, o]
    {
        const float* Tsm = &Tpart[0][0];
        const int o = tid >> 4, ik = tid & 15, i = ik >> 2, k = ik & 3;
        const float* wp = wgt + (size_t)((c * COUT + o) * 4) * 4;
        float contrib = 0.f;
        #pragma unroll
        for (int j = 0; j < 4; j++)
            contrib = fmaf(wp[j * 4 + k], Tsm[(i * 4 + j) * 16 + o], contrib);
        d_sc[wpar][((size_t)n * CIN + c) * 256 + tid] = contrib;
    }
}

// ---------------------------------------------------------------------------
// Finalize: rescale a (softmax normalization deferred from last k_iter) and
// emit g = squash of last iteration's field. grid (CIN, NN), 256 threads.
// ---------------------------------------------------------------------------
__global__ void k_fin(float* __restrict__ a_out,
                      float* __restrict__ g_out,
                      int rpar)
{
    const int c = blockIdx.x, n = blockIdx.y;
    const int tid = threadIdx.x;
    __shared__ float kmaxs[16], sinvs[16], ff[16];

    {
        const int o = tid >> 4, ch = tid & 15;
        const float* pmp = d_pmax[rpar] + (n * COUT + o) * CIN + ch;
        const float* psp = d_psum[rpar] + (n * COUT + o) * CIN + ch;
        float m0 = pmp[0], m1 = pmp[16];
        float gm = fmaxf(m0, m1);
        #pragma unroll
        for (int off = 8; off; off >>= 1)
            gm = fmaxf(gm, __shfl_xor_sync(0xffffffffu, gm, off));
        float e = psp[0] * __expf(m0 - gm) + psp[16] * __expf(m1 - gm);
        #pragma unroll
        for (int off = 8; off; off >>= 1)
            e += __shfl_xor_sync(0xffffffffu, e, off);
        if (ch == 0) { kmaxs[o] = gm; sinvs[o] = 1.0f / e; }
    }
    __syncthreads();
    if (tid < 16) {
        float K = d_pmax[rpar][(n * COUT + tid) * CIN + c];
        ff[tid] = __expf(K - kmaxs[tid]) * sinvs[tid];
    }
    __syncthreads();

    // a[m,o] = e[m,o] * exp(K_c - Kmax) / S
    {
        float* ap = a_out + (size_t)(n * MM + c * WH + tid) * COUT;
        #pragma unroll
        for (int q = 0; q < 4; q++) {
            float4 v = *reinterpret_cast<const float4*>(ap + 4 * q);
            v.x *= ff[4 * q];     v.y *= ff[4 * q + 1];
            v.z *= ff[4 * q + 2]; v.w *= ff[4 * q + 3];
            *reinterpret_cast<float4*>(ap + 4 * q) = v;
        }
    }

    // g output (one c-block per n does it)
    if (c == 0) {
        const int o = tid >> 4;
        const float Km = kmaxs[o], Si = sinvs[o];
        const float* sp = d_sc[rpar] + (size_t)n * CIN * 256;
        const float* pm = d_pmax[rpar] + (n * COUT + o) * CIN;
        float sv = 0.f;
        #pragma unroll
        for (int c2 = 0; c2 < CIN; c2++) {
            float f = __expf(pm[c2] - Km);
            sv = fmaf(sp[c2 * 256 + tid], f, sv);
        }
        sv *= Si;
        float sq = sv * sv;
        #pragma unroll
        for (int off = 8; off; off >>= 1)
            sq += __shfl_xor_sync(0xffffffffu, sq, off);
        const float coef = sq / (1.f + sq) / (sqrtf(sq) + EPSF);
        g_out[(size_t)n * 256 + tid] = coef * sv;
    }
}

// ---------------------------------------------------------------------------
extern "C" void kernel_launch(void* const* d_in, const int* in_sizes, int n_in,
                              void* d_out, int out_size)
{
    (void)in_sizes; (void)n_in; (void)out_size;
    const float* l = (const float*)d_in[0];
    const float* g = (const float*)d_in[1];
    const float* w = (const float*)d_in[2];
    float* out   = (float*)d_out;
    float* a_out = out;                              // [N, M, COUT]
    float* g_out = out + (size_t)NN * MM * COUT;     // [N, COUT, DD]

    dim3 grid(CIN, NN);
    k_iter<<<grid, 256>>>(l, g, w, a_out, 0, 0, 0);  // writes parity 0
    k_iter<<<grid, 256>>>(l, g, w, a_out, 1, 1, 0);  // reads 0, writes 1
    k_iter<<<grid, 256>>>(l, g, w, a_out, 2, 0, 1);  // reads 1, writes 0, emits e
    k_fin <<<grid, 256>>>(a_out, g_out, 0);          // reads 0
}

// round 14
// speedup vs baseline: 2.4075x; 1.1445x over previous
#include <cuda_runtime.h>

#define NN   32
#define CIN  32
#define COUT 16
#define WH   256
#define MM   8192   // CIN*WH
#define EPSF 1e-6f

// Scratch (device globals). Double-buffered partials: k_iter reads parity
// (wpar^1), writes parity wpar -> no intra-launch producer/consumer race.
__device__ float d_Hc[NN * CIN * 256];             // cumulative H[n][c][ij*16+o]
__device__ float d_pmax[2][NN * COUT * CIN];       // per-(n,o,c) local max K
__device__ float d_psum[2][NN * COUT * CIN];       // per-(n,o,c) sum exp(b-K)
__device__ float d_sc[2][(size_t)NN * CIN * 256];  // per-(n,c) unnormalized s-contrib
__device__ float d_ff[NN * CIN * COUT];            // per-(n,c,o) softmax rescale factor

typedef unsigned long long ull;

__device__ __forceinline__ ull pack2(float x) {
    ull p;
    asm("mov.b64 %0, {%1, %1};" : "=l"(p) : "r"(__float_as_uint(x)));
    return p;
}
__device__ __forceinline__ void fma2(ull& acc, ull a, ull b) {
    asm("fma.rn.f32x2 %0, %1, %2, %0;" : "+l"(acc) : "l"(a), "l"(b));
}
__device__ __forceinline__ void unpack2(ull v, float& lo, float& hi) {
    unsigned ulo, uhi;
    asm("mov.b64 {%0, %1}, %2;" : "=r"(ulo), "=r"(uhi) : "l"(v));
    lo = __uint_as_float(ulo); hi = __uint_as_float(uhi);
}

// ---------------------------------------------------------------------------
// One fused routing iteration. grid (CIN, NN), 256 threads.
//  it>0: finalize prev stats -> ffs table; g = squash(sum_c sc_u*ff)
//  H_t = W·g; Hcum += H_t; b = <L, Hcum>
//  K = block max(b); e = exp(b-K)  [sum folded into phase-2 ones column]
//  T_u = sum_s e*L (col 16 = sum e); sc_u = W-contract(T_u)
//  write_a: store unnormalized e to a_out (k_scale rescales later)
// ---------------------------------------------------------------------------
__global__ void __launch_bounds__(256, 4)
k_iter(const float* __restrict__ l,
       const float* __restrict__ g0,
       const float* __restrict__ wgt,
       float* __restrict__ a_out,
       int it, int wpar, int write_a)
{
    const int c = blockIdx.x, n = blockIdx.y;
    const int tid = threadIdx.x;
    const int lane = tid & 31, warp = tid >> 5;

    __shared__ __align__(16) float ccs[256][18];   // e[s][o]
    __shared__ __align__(16) float Ls[256][18];    // L[s][ij], col 16 = 1.0f
    __shared__ float Tpart[8][272];                // per-warp T partials (+sum row)
    __shared__ float Hsm[256];                     // Hcum[(ij)*16+o]
    __shared__ float gsm[256];                     // g[o*16+ik]
    __shared__ float red[COUT][8];
    __shared__ float kms[COUT];                    // local block max
    __shared__ float ffs[CIN][COUT];               // prologue rescale factors

    if (it > 0) {
        const int rpar = wpar ^ 1;
        // Finalize global Kmax / S for this n; build ffs[c][o] = exp(K-Km)/S
        {
            const int o = tid >> 4, ch = tid & 15;
            const float* pmp = d_pmax[rpar] + (n * COUT + o) * CIN + ch;
            const float* psp = d_psum[rpar] + (n * COUT + o) * CIN + ch;
            float m0 = pmp[0], m1 = pmp[16];
            float gm = fmaxf(m0, m1);
            #pragma unroll
            for (int off = 8; off; off >>= 1)
                gm = fmaxf(gm, __shfl_xor_sync(0xffffffffu, gm, off));
            float f0 = __expf(m0 - gm), f1 = __expf(m1 - gm);
            float e = psp[0] * f0 + psp[16] * f1;
            #pragma unroll
            for (int off = 8; off; off >>= 1)
                e += __shfl_xor_sync(0xffffffffu, e, off);   // all lanes get total
            const float Si = 1.0f / e;
            ffs[ch][o]      = f0 * Si;
            ffs[ch + 16][o] = f1 * Si;
        }
        __syncthreads();
        // g = squash( sum_c sc_u[c] * ffs[c][o] )
        {
            const int o = tid >> 4;
            const float* sp = d_sc[rpar] + (size_t)n * CIN * 256;
            float sv = 0.f;
            #pragma unroll
            for (int c2 = 0; c2 < CIN; c2++)
                sv = fmaf(sp[c2 * 256 + tid], ffs[c2][o], sv);
            float sq = sv * sv;
            #pragma unroll
            for (int off = 8; off; off >>= 1)
                sq += __shfl_xor_sync(0xffffffffu, sq, off);
            const float coef = sq / (1.f + sq) / (sqrtf(sq) + EPSF);
            gsm[tid] = coef * sv;
        }
        __syncthreads();
    }

    // H_t element + Hcum update (own slice only)
    {
        const int o = tid >> 4, i = (tid >> 2) & 3, j = tid & 3;
        const float* wp = wgt + ((size_t)(c * COUT + o) * 4 + j) * 4;
        const float* gp = (it > 0) ? (gsm + o * 16 + i * 4)
                                   : (g0 + (size_t)(n * COUT + o) * 16 + i * 4);
        float h = 0.f;
        #pragma unroll
        for (int k = 0; k < 4; k++) h = fmaf(wp[k], gp[k], h);
        const int idx = (i * 4 + j) * 16 + o;
        float* hc = d_Hc + (size_t)(n * CIN + c) * 256;
        if (it > 0) h += hc[idx];
        hc[idx] = h;
        Hsm[idx] = h;
    }

    // Load L[t] = l[n,c,t,s=tid]; stash to Ls; ones column for sum-fold
    float L[16];
    const float* lp = l + ((size_t)(n * CIN + c) * 16) * WH + tid;
    #pragma unroll
    for (int t = 0; t < 16; t++) { L[t] = lp[t * WH]; Ls[tid][t] = L[t]; }
    Ls[tid][16] = 1.0f;
    __syncthreads();   // Hsm (+gsm consumed) ready

    // b = <L, Hcum>
    ull acc[8];
    #pragma unroll
    for (int p = 0; p < 8; p++) acc[p] = 0ull;
    #pragma unroll
    for (int t = 0; t < 16; t++) {
        ull Lt = pack2(L[t]);
        #pragma unroll
        for (int p = 0; p < 8; p++)
            fma2(acc[p], Lt, *reinterpret_cast<const ull*>(&Hsm[t * 16 + 2 * p]));
    }

    // Local (block) max per o
    #pragma unroll
    for (int p = 0; p < 8; p++) {
        float b0, b1;
        unpack2(acc[p], b0, b1);
        #pragma unroll
        for (int off = 16; off; off >>= 1) {
            b0 = fmaxf(b0, __shfl_xor_sync(0xffffffffu, b0, off));
            b1 = fmaxf(b1, __shfl_xor_sync(0xffffffffu, b1, off));
        }
        if (lane == 0) { red[2 * p][warp] = b0; red[2 * p + 1][warp] = b1; }
    }
    __syncthreads();
    if (tid < 16) {
        float v = red[tid][0];
        #pragma unroll
        for (int w = 1; w < 8; w++) v = fmaxf(v, red[tid][w]);
        kms[tid] = v;
        d_pmax[wpar][(n * COUT + tid) * CIN + c] = v;
    }
    __syncthreads();

    // e = exp(b - K); stash to ccs (sum handled by phase-2 ones column)
    float e2[16];
    #pragma unroll
    for (int p = 0; p < 8; p++) {
        float b0, b1;
        unpack2(acc[p], b0, b1);
        e2[2 * p]     = __expf(b0 - kms[2 * p]);
        e2[2 * p + 1] = __expf(b1 - kms[2 * p + 1]);
        ccs[tid][2 * p]     = e2[2 * p];
        ccs[tid][2 * p + 1] = e2[2 * p + 1];
    }
    if (write_a) {   // unnormalized e; k_scale rescales
        float* ap = a_out + (size_t)(n * MM + c * WH + tid) * COUT;
        #pragma unroll
        for (int q = 0; q < 4; q++)
            *reinterpret_cast<float4*>(ap + 4 * q) =
                make_float4(e2[4*q], e2[4*q+1], e2[4*q+2], e2[4*q+3]);
    }
    __syncthreads();

    // Phase 2: T_u[ij,o] = sum_s e[s,o]*L[s,ij]; col16 accumulates sum(e).
    {
        const int p = lane & 7, q = lane >> 3;
        const ull ONES = pack2(1.0f);
        ull a2[4], aS = 0ull;
        #pragma unroll
        for (int e = 0; e < 4; e++) a2[e] = 0ull;
        const int s0 = warp * 32;
        #pragma unroll 4
        for (int s = s0; s < s0 + 32; s++) {
            ull ccp = *reinterpret_cast<const ull*>(&ccs[s][2 * p]);
            ull l01 = *reinterpret_cast<const ull*>(&Ls[s][4 * q]);
            ull l23 = *reinterpret_cast<const ull*>(&Ls[s][4 * q + 2]);
            float l0, l1, l2, l3;
            unpack2(l01, l0, l1);
            unpack2(l23, l2, l3);
            fma2(a2[0], pack2(l0), ccp);
            fma2(a2[1], pack2(l1), ccp);
            fma2(a2[2], pack2(l2), ccp);
            fma2(a2[3], pack2(l3), ccp);
            if (q == 0) fma2(aS, ONES, ccp);
        }
        #pragma unroll
        for (int e = 0; e < 4; e++)
            *reinterpret_cast<ull*>(&Tpart[warp][(4 * q + e) * 16 + 2 * p]) = a2[e];
        if (q == 0)
            *reinterpret_cast<ull*>(&Tpart[warp][256 + 2 * p]) = aS;
    }
    __syncthreads();
    {
        float v = 0.f;
        #pragma unroll
        for (int w = 0; w < 8; w++) v += Tpart[w][tid];
        Tpart[0][tid] = v;   // T_u[ij*16+o]
        if (tid < 16) {
            float sm = 0.f;
            #pragma unroll
            for (int w = 0; w < 8; w++) sm += Tpart[w][256 + tid];
            d_psum[wpar][(n * COUT + tid) * CIN + c] = sm;
        }
    }
    __syncthreads();
    // sc_u[o,ik] = sum_j W[c,o,j,k] * T_u[i*4+j, o]
    {
        const float* Tsm = &Tpart[0][0];
        const int o = tid >> 4, ik = tid & 15, i = ik >> 2, k = ik & 3;
        const float* wp = wgt + (size_t)((c * COUT + o) * 4) * 4;
        float contrib = 0.f;
        #pragma unroll
        for (int j = 0; j < 4; j++)
            contrib = fmaf(wp[j * 4 + k], Tsm[(i * 4 + j) * 16 + o], contrib);
        d_sc[wpar][((size_t)n * CIN + c) * 256 + tid] = contrib;
    }
}

// ---------------------------------------------------------------------------
// k_stats: finalize last iteration's softmax stats -> d_ff; emit g_out.
// grid NN, 512 threads (warp = o, lane = c).
// ---------------------------------------------------------------------------
__global__ void k_stats(float* __restrict__ g_out, int rpar)
{
    const int n = blockIdx.x;
    const int tid = threadIdx.x;
    __shared__ float ffs[CIN][COUT];

    {
        const int o = tid >> 5, cc = tid & 31;
        float pm = d_pmax[rpar][(n * COUT + o) * CIN + cc];
        float ps = d_psum[rpar][(n * COUT + o) * CIN + cc];
        float gm = pm;
        #pragma unroll
        for (int off = 16; off; off >>= 1)
            gm = fmaxf(gm, __shfl_xor_sync(0xffffffffu, gm, off));
        float f = __expf(pm - gm);
        float e = ps * f;
        #pragma unroll
        for (int off = 16; off; off >>= 1)
            e += __shfl_xor_sync(0xffffffffu, e, off);
        const float ffv = f / e;
        ffs[cc][o] = ffv;
        d_ff[(n * CIN + cc) * COUT + o] = ffv;
    }
    __syncthreads();

    if (tid < 256) {
        const int o = tid >> 4;
        const float* sp = d_sc[rpar] + (size_t)n * CIN * 256;
        float sv = 0.f;
        #pragma unroll
        for (int c2 = 0; c2 < CIN; c2++)
            sv = fmaf(sp[c2 * 256 + tid], ffs[c2][o], sv);
        float sq = sv * sv;
        #pragma unroll
        for (int off = 8; off; off >>= 1)
            sq += __shfl_xor_sync(0xffffffffu, sq, off);
        const float coef = sq / (1.f + sq) / (sqrtf(sq) + EPSF);
        g_out[(size_t)n * 256 + tid] = coef * sv;
    }
}

// ---------------------------------------------------------------------------
// k_scale: a[m,o] = e[m,o] * ff[n,c,o]. Pure streaming RMW, no reductions.
// grid (CIN, NN), 256 threads.
// ---------------------------------------------------------------------------
__global__ void k_scale(float* __restrict__ a_out)
{
    const int c = blockIdx.x, n = blockIdx.y;
    const int tid = threadIdx.x;
    __shared__ float ffb[COUT];

    if (tid < COUT) ffb[tid] = d_ff[(n * CIN + c) * COUT + tid];
    __syncthreads();

    float* ap = a_out + (size_t)(n * MM + c * WH + tid) * COUT;
    #pragma unroll
    for (int q = 0; q < 4; q++) {
        float4 v = *reinterpret_cast<const float4*>(ap + 4 * q);
        v.x *= ffb[4 * q];     v.y *= ffb[4 * q + 1];
        v.z *= ffb[4 * q + 2]; v.w *= ffb[4 * q + 3];
        *reinterpret_cast<float4*>(ap + 4 * q) = v;
    }
}

// ---------------------------------------------------------------------------
extern "C" void kernel_launch(void* const* d_in, const int* in_sizes, int n_in,
                              void* d_out, int out_size)
{
    (void)in_sizes; (void)n_in; (void)out_size;
    const float* l = (const float*)d_in[0];
    const float* g = (const float*)d_in[1];
    const float* w = (const float*)d_in[2];
    float* out   = (float*)d_out;
    float* a_out = out;                              // [N, M, COUT]
    float* g_out = out + (size_t)NN * MM * COUT;     // [N, COUT, DD]

    dim3 grid(CIN, NN);
    k_iter<<<grid, 256>>>(l, g, w, a_out, 0, 0, 0);  // writes parity 0
    k_iter<<<grid, 256>>>(l, g, w, a_out, 1, 1, 0);  // reads 0, writes 1
    k_iter<<<grid, 256>>>(l, g, w, a_out, 2, 0, 1);  // reads 1, writes 0, emits e
    k_stats<<<NN, 512>>>(g_out, 0);                  // d_ff + g
    k_scale<<<grid, 256>>>(a_out);                   // normalize a
}

// round 17
// speedup vs baseline: 2.9048x; 1.2066x over previous
#include <cuda_runtime.h>

#define NN   32
#define CIN  32
#define COUT 16
#define WH   256
#define MM   8192   // CIN*WH
#define EPSF 1e-6f

// Scratch (device globals). Double-buffered partials: k_iter reads parity
// (wpar^1), writes parity wpar -> no intra-launch producer/consumer race.
// Shift K is per-(n,o) UNIFORM (0 at it0; running log-sum-exp afterwards),
// so partial sums combine by plain addition and the final softmax
// normalization is a single uniform 1/S per (n,o)  -> merged k_norm.
__device__ float d_Hc[NN * CIN * 256];             // cumulative H[n][c][ij*16+o]
__device__ float d_psum[2][NN * COUT * CIN];       // per-(n,o,c) sum exp(b-K)
__device__ float d_sc[2][(size_t)NN * CIN * 256];  // per-(n,c) unnormalized s-contrib
__device__ float d_K[2][NN * COUT];                // shift used by that parity's iter

typedef unsigned long long ull;

__device__ __forceinline__ ull pack2(float x) {
    ull p;
    asm("mov.b64 %0, {%1, %1};" : "=l"(p) : "r"(__float_as_uint(x)));
    return p;
}
__device__ __forceinline__ void fma2(ull& acc, ull a, ull b) {
    asm("fma.rn.f32x2 %0, %1, %2, %0;" : "+l"(acc) : "l"(a), "l"(b));
}
__device__ __forceinline__ void unpack2(ull v, float& lo, float& hi) {
    unsigned ulo, uhi;
    asm("mov.b64 {%0, %1}, %2;" : "=r"(ulo), "=r"(uhi) : "l"(v));
    lo = __uint_as_float(ulo); hi = __uint_as_float(uhi);
}

// ---------------------------------------------------------------------------
// One fused routing iteration. grid (CIN, NN), 256 threads.
//  it>0: S = sum_c psum; Si = 1/S; K_new = K_prev + log(S) (uniform LSE shift)
//        g = squash((sum_c sc_u) * Si)
//  H_t = W·g; Hcum += H_t; b = <L, Hcum>; e = exp(b - K)
//  T_u = sum_s e*L (ones column accumulates sum e); sc_u = W-contract(T_u)
//  write_a: store unnormalized e to a_out (k_norm rescales)
// ---------------------------------------------------------------------------
__global__ void __launch_bounds__(256, 4)
k_iter(const float* __restrict__ l,
       const float* __restrict__ g0,
       const float* __restrict__ wgt,
       float* __restrict__ a_out,
       int it, int wpar, int write_a)
{
    const int c = blockIdx.x, n = blockIdx.y;
    const int tid = threadIdx.x;
    const int lane = tid & 31, warp = tid >> 5;

    __shared__ __align__(16) float ccs[256][18];   // e[s][o]
    __shared__ __align__(16) float Ls[256][18];    // L[s][ij], col 16 = 1.0f
    __shared__ float Tpart[8][272];                // per-warp T partials (+sum row)
    __shared__ __align__(16) float Hsm[256];       // Hcum[(ij)*16+o]
    __shared__ float gsm[256];                     // g[o*16+ik]
    __shared__ float Sis[COUT];                    // 1/S per o
    __shared__ float Ksm[COUT];                    // shift K for this iteration

    if (it > 0) {
        const int rpar = wpar ^ 1;
        // S[o] = sum_c psum[c]; Si = 1/S; K_new = K_prev + log(S)
        {
            const int o = tid >> 4, ch = tid & 15;
            const float* psp = d_psum[rpar] + (n * COUT + o) * CIN + ch;
            float e = psp[0] + psp[16];
            #pragma unroll
            for (int off = 8; off; off >>= 1)
                e += __shfl_xor_sync(0xffffffffu, e, off);
            if (ch == 0) {
                Sis[o] = 1.0f / e;
                float Kn = d_K[rpar][n * COUT + o] + __logf(e);
                Ksm[o] = Kn;
                if (c == 0) d_K[wpar][n * COUT + o] = Kn;  // for next iteration
            }
        }
        __syncthreads();
        // g = squash( (sum_c sc_u[c]) * Si[o] )
        {
            const int o = tid >> 4;
            const float* sp = d_sc[rpar] + (size_t)n * CIN * 256;
            float sv = 0.f;
            #pragma unroll
            for (int c2 = 0; c2 < CIN; c2++) sv += sp[c2 * 256 + tid];
            sv *= Sis[o];
            float sq = sv * sv;
            #pragma unroll
            for (int off = 8; off; off >>= 1)
                sq += __shfl_xor_sync(0xffffffffu, sq, off);
            const float coef = sq / (1.f + sq) / (sqrtf(sq) + EPSF);
            gsm[tid] = coef * sv;
        }
        __syncthreads();
    } else {
        if (tid < COUT) {
            Ksm[tid] = 0.0f;
            if (c == 0) d_K[wpar][n * COUT + tid] = 0.0f;
        }
        __syncthreads();
    }

    // H_t element + Hcum update (own slice only)
    {
        const int o = tid >> 4, i = (tid >> 2) & 3, j = tid & 3;
        const float* wp = wgt + ((size_t)(c * COUT + o) * 4 + j) * 4;
        const float* gp = (it > 0) ? (gsm + o * 16 + i * 4)
                                   : (g0 + (size_t)(n * COUT + o) * 16 + i * 4);
        float h = 0.f;
        #pragma unroll
        for (int k = 0; k < 4; k++) h = fmaf(wp[k], gp[k], h);
        const int idx = (i * 4 + j) * 16 + o;
        float* hc = d_Hc + (size_t)(n * CIN + c) * 256;
        if (it > 0) h += hc[idx];
        hc[idx] = h;
        Hsm[idx] = h;
    }

    // Load L[t] = l[n,c,t,s=tid]; stash to Ls; ones column for sum-fold
    float L[16];
    const float* lp = l + ((size_t)(n * CIN + c) * 16) * WH + tid;
    #pragma unroll
    for (int t = 0; t < 16; t++) { L[t] = lp[t * WH]; Ls[tid][t] = L[t]; }
    Ls[tid][16] = 1.0f;
    __syncthreads();   // Hsm (+gsm consumed) ready

    // b = <L, Hcum>: Hsm rows read as 4x LDS.128 (ull pairs, no MOVs)
    ull acc[8];
    #pragma unroll
    for (int p = 0; p < 8; p++) acc[p] = 0ull;
    #pragma unroll
    for (int t = 0; t < 16; t++) {
        ull Lt = pack2(L[t]);
        ulonglong2 hA = *reinterpret_cast<const ulonglong2*>(&Hsm[t * 16 + 0]);
        ulonglong2 hB = *reinterpret_cast<const ulonglong2*>(&Hsm[t * 16 + 4]);
        ulonglong2 hC = *reinterpret_cast<const ulonglong2*>(&Hsm[t * 16 + 8]);
        ulonglong2 hD = *reinterpret_cast<const ulonglong2*>(&Hsm[t * 16 + 12]);
        fma2(acc[0], Lt, hA.x); fma2(acc[1], Lt, hA.y);
        fma2(acc[2], Lt, hB.x); fma2(acc[3], Lt, hB.y);
        fma2(acc[4], Lt, hC.x); fma2(acc[5], Lt, hC.y);
        fma2(acc[6], Lt, hD.x); fma2(acc[7], Lt, hD.y);
    }

    // e = exp(b - K); stash to ccs (sum handled by phase-2 ones column)
    float e2[16];
    #pragma unroll
    for (int p = 0; p < 8; p++) {
        float b0, b1;
        unpack2(acc[p], b0, b1);
        e2[2 * p]     = __expf(b0 - Ksm[2 * p]);
        e2[2 * p + 1] = __expf(b1 - Ksm[2 * p + 1]);
        ccs[tid][2 * p]     = e2[2 * p];
        ccs[tid][2 * p + 1] = e2[2 * p + 1];
    }
    if (write_a) {   // unnormalized e; k_norm rescales
        float* ap = a_out + (size_t)(n * MM + c * WH + tid) * COUT;
        #pragma unroll
        for (int q = 0; q < 4; q++)
            *reinterpret_cast<float4*>(ap + 4 * q) =
                make_float4(e2[4*q], e2[4*q+1], e2[4*q+2], e2[4*q+3]);
    }
    __syncthreads();

    // Phase 2: T_u[ij,o] = sum_s e[s,o]*L[s,ij]; col16 accumulates sum(e).
    {
        const int p = lane & 7, q = lane >> 3;
        const ull ONES = pack2(1.0f);
        ull a2[4], aS = 0ull;
        #pragma unroll
        for (int e = 0; e < 4; e++) a2[e] = 0ull;
        const int s0 = warp * 32;
        #pragma unroll 4
        for (int s = s0; s < s0 + 32; s++) {
            ull ccp = *reinterpret_cast<const ull*>(&ccs[s][2 * p]);
            ull l01 = *reinterpret_cast<const ull*>(&Ls[s][4 * q]);
            ull l23 = *reinterpret_cast<const ull*>(&Ls[s][4 * q + 2]);
            float l0, l1, l2, l3;
            unpack2(l01, l0, l1);
            unpack2(l23, l2, l3);
            fma2(a2[0], pack2(l0), ccp);
            fma2(a2[1], pack2(l1), ccp);
            fma2(a2[2], pack2(l2), ccp);
            fma2(a2[3], pack2(l3), ccp);
            if (q == 0) fma2(aS, ONES, ccp);
        }
        #pragma unroll
        for (int e = 0; e < 4; e++)
            *reinterpret_cast<ull*>(&Tpart[warp][(4 * q + e) * 16 + 2 * p]) = a2[e];
        if (q == 0)
            *reinterpret_cast<ull*>(&Tpart[warp][256 + 2 * p]) = aS;
    }
    __syncthreads();
    {
        float v = 0.f;
        #pragma unroll
        for (int w = 0; w < 8; w++) v += Tpart[w][tid];
        Tpart[0][tid] = v;   // T_u[ij*16+o]
        if (tid < 16) {
            float sm = 0.f;
            #pragma unroll
            for (int w = 0; w < 8; w++) sm += Tpart[w][256 + tid];
            d_psum[wpar][(n * COUT + tid) * CIN + c] = sm;
        }
    }
    __syncthreads();
    // sc_u[o,ik] = sum_j W[c,o,j,k] * T_u[i*4+j, o]
    {
        const float* Tsm = &Tpart[0][0];
        const int o = tid >> 4, ik = tid & 15, i = ik >> 2, k = ik & 3;
        const float* wp = wgt + (size_t)((c * COUT + o) * 4) * 4;
        float contrib = 0.f;
        #pragma unroll
        for (int j = 0; j < 4; j++)
            contrib = fmaf(wp[j * 4 + k], Tsm[(i * 4 + j) * 16 + o], contrib);
        d_sc[wpar][((size_t)n * CIN + c) * 256 + tid] = contrib;
    }
}

// ---------------------------------------------------------------------------
// k_norm: Si = 1/sum_c psum (tiny redundant prologue per block, uniform K);
// a[m,o] = e[m,o] * Si[o]; c==0 blocks also emit g = squash(sum_c sc * Si).
// grid (CIN, NN), 256 threads.
// ---------------------------------------------------------------------------
__global__ void k_norm(float* __restrict__ a_out,
                       float* __restrict__ g_out,
                       int rpar)
{
    const int c = blockIdx.x, n = blockIdx.y;
    const int tid = threadIdx.x;
    __shared__ float Sis[COUT];

    {
        const int o = tid >> 4, ch = tid & 15;
        const float* psp = d_psum[rpar] + (n * COUT + o) * CIN + ch;
        float e = psp[0] + psp[16];
        #pragma unroll
        for (int off = 8; off; off >>= 1)
            e += __shfl_xor_sync(0xffffffffu, e, off);
        if (ch == 0) Sis[o] = 1.0f / e;
    }
    __syncthreads();

    // a normalize (streaming RMW)
    {
        float* ap = a_out + (size_t)(n * MM + c * WH + tid) * COUT;
        #pragma unroll
        for (int q = 0; q < 4; q++) {
            float4 v = *reinterpret_cast<const float4*>(ap + 4 * q);
            v.x *= Sis[4 * q];     v.y *= Sis[4 * q + 1];
            v.z *= Sis[4 * q + 2]; v.w *= Sis[4 * q + 3];
            *reinterpret_cast<float4*>(ap + 4 * q) = v;
        }
    }

    // g output (one c-block per n)
    if (c == 0) {
        const int o = tid >> 4;
        const float* sp = d_sc[rpar] + (size_t)n * CIN * 256;
        float sv = 0.f;
        #pragma unroll
        for (int c2 = 0; c2 < CIN; c2++) sv += sp[c2 * 256 + tid];
        sv *= Sis[o];
        float sq = sv * sv;
        #pragma unroll
        for (int off = 8; off; off >>= 1)
            sq += __shfl_xor_sync(0xffffffffu, sq, off);
        const float coef = sq / (1.f + sq) / (sqrtf(sq) + EPSF);
        g_out[(size_t)n * 256 + tid] = coef * sv;
    }
}

// ---------------------------------------------------------------------------
extern "C" void kernel_launch(void* const* d_in, const int* in_sizes, int n_in,
                              void* d_out, int out_size)
{
    (void)in_sizes; (void)n_in; (void)out_size;
    const float* l = (const float*)d_in[0];
    const float* g = (const float*)d_in[1];
    const float* w = (const float*)d_in[2];
    float* out   = (float*)d_out;
    float* a_out = out;                              // [N, M, COUT]
    float* g_out = out + (size_t)NN * MM * COUT;     // [N, COUT, DD]

    dim3 grid(CIN, NN);
    k_iter<<<grid, 256>>>(l, g, w, a_out, 0, 0, 0);  // writes parity 0
    k_iter<<<grid, 256>>>(l, g, w, a_out, 1, 1, 0);  // reads 0, writes 1
    k_iter<<<grid, 256>>>(l, g, w, a_out, 2, 0, 1);  // reads 1, writes 0, emits e
    k_norm<<<grid, 256>>>(a_out, g_out, 0);          // normalize a + emit g
}